// round 8
// baseline (speedup 1.0000x reference)
#include <cuda_runtime.h>

// StDevLoss: 7x7 clamped-window 3D-point-distance std, summed, x100.
// depthin (1,1,480,640) fp32 -> scalar fp32. Single fused kernel.
// Round 8: scalar expanded-distance form (no pack/unpack movs), abs-folded
// sqrt guard, hoisted column factors. 2 px/thread, 1200 blocks.

#define ROWS 480
#define COLS 640

#define BX 32
#define BY 4
#define NT (BX * BY)          // 128 threads
#define PIX_Y 8               // 2 pixels per thread
#define TW (BX + 6)           // 38
#define TH (PIX_Y + 6)        // 14
#define TP 40                 // shared row stride (float2 units)

#define GRIDX (COLS / BX)     // 20
#define GRIDY (ROWS / PIX_Y)  // 60
#define NPART (GRIDX * GRIDY) // 1200

__device__ float g_partials[NPART];
__device__ unsigned int g_count = 0;

// sqrt(|x|): the abs folds into the MUFU operand modifier -> single MUFU,
// no clamp instruction needed, and sqrt(|tiny_negative_residue|) ~ 0.
__device__ __forceinline__ float sqrt_abs(float x) {
    float r;
    asm("{\n\t"
        ".reg .f32 t;\n\t"
        "abs.f32 t, %1;\n\t"
        "sqrt.approx.f32 %0, t;\n\t"
        "}" : "=f"(r) : "f"(x));
    return r;
}

__global__ __launch_bounds__(NT, 9)
void stdev_kernel(const float* __restrict__ depth, float* __restrict__ out) {
    const float CXc   = 313.0447587080473f;
    const float CYc   = 238.44389626620386f;
    const float invFX = 1.0f / 582.6244816773795f;
    const float invFY = 1.0f / 582.6910327098864f;

    __shared__ float2 shz[TH * TP];      // (z, z^2)
    __shared__ float red[NT / 32];
    __shared__ unsigned int s_last;

    const int tx  = threadIdx.x;
    const int ty  = threadIdx.y;
    const int tid = ty * BX + tx;
    const int c0  = blockIdx.x * BX;
    const int r0  = blockIdx.y * PIX_Y;

    // Cooperative haloed (z, z^2) tile load. Clamped halo cells are never
    // read by the clamped-window indexing but must hold finite values.
    for (int i = tid; i < TH * TW; i += NT) {
        const int sr = i / TW;
        const int sc = i - sr * TW;
        const int gr = min(max(r0 - 3 + sr, 0), ROWS - 1);
        const int gc = min(max(c0 - 3 + sc, 0), COLS - 1);
        const float d = depth[gr * COLS + gc];
        const float z = (d > 0.0f && d < 1.01f) ? d * 1e-3f : 0.0f;
        shz[sr * TP + sc] = make_float2(z, z * z);
    }
    __syncthreads();

    const int c    = c0 + tx;
    const int jb   = min(max(c - 3, 0), COLS - 7);
    const int jb_s = jb - c0 + 3;
    const float cfc = ((float)c - CXc) * invFX;     // center column factor
    const float cf0 = ((float)jb - CXc) * invFX;    // window column factor base

    // Pixel-independent per-column g_j = cf_j^2 + 1, and the cf_j themselves.
    float cfj[7], gj[7];
    {
        float cf = cf0;
        #pragma unroll
        for (int j = 0; j < 7; j++) {
            cfj[j] = cf;
            gj[j]  = fmaf(cf, cf, 1.0f);
            cf += invFX;
        }
    }

    float total = 0.0f;

    #pragma unroll
    for (int p = 0; p < 2; p++) {
        const int r    = r0 + ty + p * BY;
        const int ib   = min(max(r - 3, 0), ROWS - 7);
        const int ib_s = ib - r0 + 3;

        const float zc = shz[(ty + p * BY + 3) * TP + (tx + 3)].x;
        const float xc = zc * cfc;
        const float yc = zc * (((float)r - CYc) * invFY);
        float pc2 = xc * xc;
        pc2 = fmaf(yc, yc, pc2);
        pc2 = fmaf(zc, zc, pc2);
        const float m2xc = -2.0f * xc;
        const float m2yc = -2.0f * yc;
        const float m2zc = -2.0f * zc;

        // Per-column b_j = -2*xc*cf_j (pixel-specific).
        float bj[7];
        #pragma unroll
        for (int j = 0; j < 7; j++)
            bj[j] = m2xc * cfj[j];

        float s1a = 0.0f, s1b = 0.0f;   // sum d
        float s2a = 0.0f, s2b = 0.0f;   // sum d^2 (= sum ss)

        float rf = ((float)ib - CYc) * invFY;
        #pragma unroll
        for (int i = 0; i < 7; i++) {
            const float ai = fmaf(m2yc, rf, m2zc);   // -2*(yc*rf + zc)
            const float r2 = rf * rf;
            rf += invFY;
            const float2* __restrict__ rowp = &shz[(ib_s + i) * TP + jb_s];
            #pragma unroll
            for (int j = 0; j < 7; j++) {
                const float2 zz = rowp[j];            // (zn, zn^2)
                const float m  = ai + bj[j];
                const float g  = r2 + gj[j];
                float ss = fmaf(zz.x, m, pc2);
                ss = fmaf(zz.y, g, ss);
                const float dd = sqrt_abs(ss);
                if (j & 1) { s1a += dd; s2a += ss; }
                else       { s1b += dd; s2b += ss; }
            }
        }

        const float s1 = s1a + s1b;
        const float s2 = s2a + s2b;

        // var = (sum d^2 - (sum d)^2/49) / 48  (Bessel-corrected)
        const float mean = s1 * (1.0f / 49.0f);
        float var = fmaf(-mean, s1, s2) * (1.0f / 48.0f);
        var = fmaxf(var, 0.0f);
        total += (zc > 0.0f) ? sqrt_abs(var) : 0.0f;
    }

    // Deterministic warp shuffle reduction, then cross-warp via smem.
    #pragma unroll
    for (int k = 16; k > 0; k >>= 1)
        total += __shfl_down_sync(0xFFFFFFFFu, total, k);
    if ((tid & 31) == 0) red[tid >> 5] = total;
    __syncthreads();

    // Fused final reduction: last arriving block sums all partials in
    // fixed index order (deterministic), writes out, re-arms counter.
    if (tid == 0) {
        g_partials[blockIdx.y * GRIDX + blockIdx.x] =
            (red[0] + red[1]) + (red[2] + red[3]);
        __threadfence();
        const unsigned int t = atomicAdd(&g_count, 1u);
        s_last = (t == NPART - 1) ? 1u : 0u;
    }
    __syncthreads();

    if (s_last) {
        const volatile float* vp = g_partials;
        float s = 0.0f;
        for (int i = tid; i < NPART; i += NT) s += vp[i];
        #pragma unroll
        for (int k = 16; k > 0; k >>= 1)
            s += __shfl_down_sync(0xFFFFFFFFu, s, k);
        if ((tid & 31) == 0) red[tid >> 5] = s;
        __syncthreads();
        if (tid == 0) {
            out[0] = ((red[0] + red[1]) + (red[2] + red[3])) * 100.0f;
            g_count = 0;   // re-arm for next graph replay
        }
    }
}

extern "C" void kernel_launch(void* const* d_in, const int* in_sizes, int n_in,
                              void* d_out, int out_size) {
    const float* depth = (const float*)d_in[0];
    float* out = (float*)d_out;

    dim3 grid(GRIDX, GRIDY);
    dim3 block(BX, BY);
    stdev_kernel<<<grid, block>>>(depth, out);
}